// round 16
// baseline (speedup 1.0000x reference)
#include <cuda_runtime.h>
#include <cuda_fp16.h>
#include <math.h>
#include <stdint.h>

#define BB   4
#define NN   16384
#define CIN0 64
#define COUT 128
#define RR   32
#define NVOX (BB*RR*RR*RR)   /* 131072 */

typedef unsigned int u32;
typedef unsigned long long u64;

// ---------------- scratch (device globals) ------------------------------------
__device__ float g_grid[(size_t)NVOX * CIN0];
__device__ float g_cnt [NVOX];
__device__ __align__(16) __half g_g0[(size_t)NVOX * CIN0];    // conv1 in (fp16)
__device__ __align__(16) __half g_h1[(size_t)NVOX * COUT];    // conv2 in (fp16)
__device__ __align__(16) __half g_h2h[(size_t)NVOX * COUT];   // conv2 out (fp16)
__device__ __align__(16) __half g_pfh[(size_t)BB * NN * COUT];// point feats (fp16)
__device__ float g_stats[BB * 8 * 2];
// W layouts (27 taps): conv1 [tap][co][ci64]; conv2 [ci-half][tap][co][ci64]
__device__ __align__(16) __half g_w1[27 * COUT * 64];
__device__ __align__(16) __half g_w2[2 * 27 * COUT * 64];

// ---------------- helpers -------------------------------------------------------
__device__ __forceinline__ u32 smem_u32(const void* p) {
    u32 a;
    asm("{ .reg .u64 t; cvta.to.shared.u64 t, %1; cvt.u32.u64 %0, t; }" : "=r"(a) : "l"(p));
    return a;
}
__device__ __forceinline__ void cp16(u32 dst, const void* src, u32 sz) {
    asm volatile("cp.async.cg.shared.global [%0], [%1], 16, %2;"
                 :: "r"(dst), "l"(src), "r"(sz) : "memory");
}
__device__ __forceinline__ void ldsm4(u32& r0, u32& r1, u32& r2, u32& r3, u32 a) {
    asm volatile("ldmatrix.sync.aligned.m8n8.x4.shared.b16 {%0,%1,%2,%3}, [%4];"
                 : "=r"(r0), "=r"(r1), "=r"(r2), "=r"(r3) : "r"(a));
}
__device__ __forceinline__ void mma16816(float* d,
                                         u32 a0, u32 a1, u32 a2, u32 a3,
                                         u32 b0, u32 b1) {
    asm volatile("mma.sync.aligned.m16n8k16.row.col.f32.f16.f16.f32 "
                 "{%0,%1,%2,%3}, {%4,%5,%6,%7}, {%8,%9}, {%0,%1,%2,%3};"
                 : "+f"(d[0]), "+f"(d[1]), "+f"(d[2]), "+f"(d[3])
                 : "r"(a0), "r"(a1), "r"(a2), "r"(a3), "r"(b0), "r"(b1));
}

#define MBAR_INIT(addr, cnt) \
    asm volatile("mbarrier.init.shared.b64 [%0], %1;" :: "r"((u32)(addr)), "r"((u32)(cnt)) : "memory")
#define MBAR_ARRIVE(addr) \
    asm volatile("mbarrier.arrive.shared.b64 _, [%0];" :: "r"((u32)(addr)) : "memory")
// .noinc: does NOT bump the expected count -> 32 lane arrivals satisfy init(32).
#define CP_MBAR_ARRIVE(addr) \
    asm volatile("cp.async.mbarrier.arrive.noinc.shared.b64 [%0];" :: "r"((u32)(addr)) : "memory")
#define MBAR_WAIT(addr, parity) do {                                          \
    u32 _m = (u32)(addr); u32 _p = (u32)(parity); u32 _done;                  \
    asm volatile("{\n\t.reg .pred p;\n\t"                                     \
        "mbarrier.try_wait.parity.acquire.cta.shared::cta.b64 p, [%1], %2;\n\t" \
        "selp.b32 %0, 1, 0, p;\n\t}" : "=r"(_done) : "r"(_m), "r"(_p) : "memory"); \
    if (!_done) {                                                             \
        asm volatile("{\n\t.reg .pred P1;\n\tWL_%=:\n\t"                      \
            "mbarrier.try_wait.parity.acquire.cta.shared::cta.b64 P1, [%0], %1, 0x989680;\n\t" \
            "@P1 bra.uni WD_%=;\n\tbra.uni WL_%=;\n\tWD_%=:\n\t}"             \
            :: "r"(_m), "r"(_p) : "memory");                                  \
    }                                                                         \
} while (0)

// ---------------- prep: zero scratch + both weight preps (ONE launch) -----------
#define NG  ((long)NVOX * CIN0)
#define NC  ((long)NVOX)
#define NS  ((long)BB * 8 * 2)
#define NW1 ((long)27 * COUT * 64)
#define NW2 ((long)2 * 27 * COUT * 64)

__global__ void prep_kernel(const float* __restrict__ w1,
                            const float* __restrict__ w2) {
    const long total = NG + NC + NS + NW1 + NW2;
    for (long i = (long)blockIdx.x * blockDim.x + threadIdx.x; i < total;
         i += (long)gridDim.x * blockDim.x) {
        if (i < NG) { g_grid[i] = 0.f; continue; }
        long j = i - NG;
        if (j < NC) { g_cnt[j] = 0.f; continue; }
        j -= NC;
        if (j < NS) { g_stats[j] = 0.f; continue; }
        j -= NS;
        if (j < NW1) {
            int tap = (int)(j >> 13);
            int r   = (int)(j & 8191);
            int co = r >> 6, ci = r & 63;
            g_w1[j] = __float2half_rn(w1[(co * 64 + ci) * 27 + tap]);
            continue;
        }
        j -= NW1;
        {
            int q  = (int)(j >> 13);
            int h  = q / 27, tapl = q - h * 27;
            int r  = (int)(j & 8191);
            int co = r >> 6, ci6 = r & 63;
            g_w2[j] = __float2half_rn(w2[(co * 128 + h * 64 + ci6) * 27 + tapl]);
        }
    }
}

// ---------------- voxelize -------------------------------------------------------
__global__ void scatter_kernel(const float* __restrict__ coords,
                               const float* __restrict__ feats) {
    int idx = blockIdx.x * blockDim.x + threadIdx.x;
    if (idx >= BB * NN * CIN0) return;
    int ci = idx & (CIN0 - 1);
    int gp = idx >> 6;
    int b  = gp >> 14;
    int n  = gp & (NN - 1);
    float cx = coords[gp * 3 + 0] * (float)RR;
    float cy = coords[gp * 3 + 1] * (float)RR;
    float cz = coords[gp * 3 + 2] * (float)RR;
    int ix = min(max((int)floorf(cx), 0), RR - 1);
    int iy = min(max((int)floorf(cy), 0), RR - 1);
    int iz = min(max((int)floorf(cz), 0), RR - 1);
    int vox = ((b * RR + ix) * RR + iy) * RR + iz;
    atomicAdd(&g_grid[(size_t)vox * CIN0 + ci],
              feats[((size_t)b * CIN0 + ci) * NN + n]);
    if (ci == 0) atomicAdd(&g_cnt[vox], 1.0f);
}

__global__ void vox_split_kernel() {
    long total = (long)NVOX * CIN0;
    for (long i = (long)blockIdx.x * blockDim.x + threadIdx.x; i < total;
         i += (long)gridDim.x * blockDim.x) {
        long v = i >> 6;
        float c = g_cnt[v];
        float val = g_grid[i] * (1.0f / fmaxf(c, 1.0f));
        g_g0[i] = __float2half_rn(val);
    }
}

// ---------------- warp-specialized mma.sync conv + GN + SiLU --------------------
// CTA: (b, x, 8y, 16z) = M128 x N128. 288 threads: warps 0-7 compute (2M x 4N,
// warp tile M64 x N32), warp 8 = producer (all cp.async).
// A: 2 plane buffers (180 rows x 128B); W: 3 tap buffers, prefetch distance 2.
// Sync via mbarriers (full/empty per buffer), producer arrivals use .noinc.
#define PITCH    144
#define APL      (180 * PITCH)        /* 25920 */
#define WOFF     (2 * APL)            /* 51840 */
#define WTEN     (128 * PITCH)        /* 18432 */
#define MBOFF    (WOFF + 3 * WTEN)    /* 107136 */
// mbarriers: full_W[3] @0, empty_W[3] @24, full_A[2] @48, empty_A[2] @64
#define CVSMEM   (MBOFF + 128)        /* 107264 */

// producer: issue one W tap (1024 x 16B units over 32 lanes)
__device__ __forceinline__ void prod_W(int nit, u32 sb, int lane, const __half* wp) {
    const u32 dst = sb + WOFF + (u32)(nit % 3) * WTEN;
    const __half* src = wp + (size_t)nit * 8192;
#pragma unroll
    for (int i = 0; i < 32; i++) {
        int u = lane + i * 32;
        int row = u >> 3, c16 = u & 7;
        cp16(dst + row * PITCH + c16 * 16, src + (size_t)row * 64 + c16 * 8, 16u);
    }
}
// producer: issue one A plane (1440 x 16B units over 32 lanes)
template <int CIN>
__device__ __forceinline__ void prod_plane(
    int np, u32 sb, int lane, int b, int x0, int y0, int z0, const __half* in) {
    const int qx = np - (np / 3) * 3;
    const int hh = np / 3;
    const int gx = x0 + qx - 1;
#pragma unroll
    for (int i = 0; i < 45; i++) {
        int u = lane + i * 32;
        int row = u >> 3, c16 = u & 7;
        int yh = row / 18, zh = row - yh * 18;
        int gy = y0 + yh - 1, gz = z0 + zh - 1;
        bool ok = ((unsigned)gx < 32u) & ((unsigned)gy < 32u) & ((unsigned)gz < 32u);
        size_t off = 0;
        if (ok)
            off = ((((size_t)(b * 32 + gx)) * 32 + gy) * 32 + gz) * CIN
                + hh * 64 + c16 * 8;
        cp16(sb + (np & 1) * APL + row * PITCH + c16 * 16, in + off, ok ? 16u : 0u);
    }
}

template <int CIN>
__global__ void __launch_bounds__(288, 2)
conv_mma_kernel(const float* __restrict__ bias,
                const float* __restrict__ gamma,
                const float* __restrict__ beta) {
    extern __shared__ __align__(128) char smem[];
    constexpr int NT  = 27 * (CIN / 64);
    constexpr int NPL = 3 * (CIN / 64);
    const u32 sb = smem_u32(smem);
    const int tid = threadIdx.x, w = tid >> 5, lane = tid & 31;
    const int x0 = blockIdx.x, y0 = blockIdx.y * 8;
    const int b  = blockIdx.z >> 1, z0 = (blockIdx.z & 1) * 16;

    const __half* in = (CIN == 64) ? g_g0 : g_h1;
    const __half* wp = (CIN == 64) ? g_w1 : g_w2;

    const u32 mb = sb + MBOFF;
    if (tid == 0) {
#pragma unroll
        for (int s = 0; s < 3; s++) {
            MBAR_INIT(mb + s * 8, 32);        // full_W[s]: 32 producer lanes
            MBAR_INIT(mb + 24 + s * 8, 8);    // empty_W[s]: 8 compute warps
        }
#pragma unroll
        for (int p = 0; p < 2; p++) {
            MBAR_INIT(mb + 48 + p * 8, 32);   // full_A[p]
            MBAR_INIT(mb + 64 + p * 8, 8);    // empty_A[p]
        }
    }
    __syncthreads();

    if (w == 8) {
        // ---------------- producer warp ----------------
        prod_plane<CIN>(0, sb, lane, b, x0, y0, z0, in);
        CP_MBAR_ARRIVE(mb + 48);              // full_A[0]
        prod_W(0, sb, lane, wp); CP_MBAR_ARRIVE(mb + 0);
        prod_W(1, sb, lane, wp); CP_MBAR_ARRIVE(mb + 8);
        prod_W(2, sb, lane, wp); CP_MBAR_ARRIVE(mb + 16);
#pragma unroll 1
        for (int it = 0; it < NT; it++) {
            if (it % 9 == 0) {
                int np = it / 9 + 1;
                if (np < NPL) {
                    if (np >= 2) MBAR_WAIT(mb + 64 + (np & 1) * 8, ((np >> 1) - 1) & 1);
                    prod_plane<CIN>(np, sb, lane, b, x0, y0, z0, in);
                    CP_MBAR_ARRIVE(mb + 48 + (np & 1) * 8);
                }
            }
            int nit = it + 3;
            if (nit < NT) {
                MBAR_WAIT(mb + 24 + (nit % 3) * 8, ((nit - 3) / 3) & 1);
                prod_W(nit, sb, lane, wp);
                CP_MBAR_ARRIVE(mb + (nit % 3) * 8);
            }
        }
        return;
    }

    // ---------------- compute warps (w = 0..7) ----------------
    const int wM = w >> 2, wN = w & 3;
    float acc[4][4][4];
#pragma unroll
    for (int mt = 0; mt < 4; mt++)
#pragma unroll
        for (int nn = 0; nn < 4; nn++)
#pragma unroll
            for (int j = 0; j < 4; j++) acc[mt][nn][j] = 0.f;

    const u32 b_row = (lane & 7) + ((lane >> 3) & 1) * 8;
    const u32 b_lane_off = (wN * 32 + b_row) * PITCH + (lane >> 4) * 16;
    u32 arel[4];
#pragma unroll
    for (int mt = 0; mt < 4; mt++)
        arel[mt] = (u32)(((wM * 4 + mt) * 18 + (lane & 15)) * PITCH)
                 + (lane >> 4) * 16;

#pragma unroll 1
    for (int it = 0; it < NT; it++) {
        const int pl = it / 9;
        if (it % 9 == 0) MBAR_WAIT(mb + 48 + (pl & 1) * 8, (pl >> 1) & 1);
        MBAR_WAIT(mb + (it % 3) * 8, (it / 3) & 1);

        const int tapl = it - (it / 27) * 27;
        const int dy   = (tapl / 3) % 3, dz = tapl % 3;
        const u32 abase = sb + (pl & 1) * APL + (u32)((dy * 18 + dz) * PITCH);
        const u32 wbase = sb + WOFF + (u32)(it % 3) * WTEN + b_lane_off;

#pragma unroll
        for (int ks = 0; ks < 4; ks++) {
            u32 a[4][4];
#pragma unroll
            for (int mt = 0; mt < 4; mt++)
                ldsm4(a[mt][0], a[mt][1], a[mt][2], a[mt][3],
                      abase + arel[mt] + ks * 32);
#pragma unroll
            for (int nt = 0; nt < 2; nt++) {
                u32 w0, w1r, w2r, w3;
                ldsm4(w0, w1r, w2r, w3, wbase + nt * 16 * PITCH + ks * 32);
#pragma unroll
                for (int mt = 0; mt < 4; mt++) {
                    mma16816(acc[mt][2 * nt],     a[mt][0], a[mt][1], a[mt][2], a[mt][3], w0, w2r);
                    mma16816(acc[mt][2 * nt + 1], a[mt][0], a[mt][1], a[mt][2], a[mt][3], w1r, w3);
                }
            }
        }
        __syncwarp();
        if (lane == 0) {
            MBAR_ARRIVE(mb + 24 + (it % 3) * 8);                 // empty_W
            if (it % 9 == 8) MBAR_ARRIVE(mb + 64 + (pl & 1) * 8); // empty_A
        }
    }

    // ---- epilogue: bias + per-voxel GN(16 ch) + SiLU, straight from fragments ----
    const int r0 = lane >> 2, cq = lane & 3;
#pragma unroll
    for (int mt = 0; mt < 4; mt++) {
        const int yl = wM * 4 + mt;
#pragma unroll
        for (int h = 0; h < 2; h++) {
            int z = r0 + h * 8;
            size_t vox = (((size_t)(b * 32 + x0)) * 32 + (y0 + yl)) * 32 + z0 + z;
#pragma unroll
            for (int k = 0; k < 2; k++) {
                int cA = wN * 32 + k * 16 + cq * 2;
                int cB = cA + 8;
                float v[4];
                v[0] = acc[mt][2 * k][2 * h + 0]     + bias[cA + 0];
                v[1] = acc[mt][2 * k][2 * h + 1]     + bias[cA + 1];
                v[2] = acc[mt][2 * k + 1][2 * h + 0] + bias[cB + 0];
                v[3] = acc[mt][2 * k + 1][2 * h + 1] + bias[cB + 1];
                float s = v[0] + v[1] + v[2] + v[3];
                float q = v[0] * v[0] + v[1] * v[1] + v[2] * v[2] + v[3] * v[3];
                s += __shfl_xor_sync(0xffffffffu, s, 1);
                s += __shfl_xor_sync(0xffffffffu, s, 2);
                q += __shfl_xor_sync(0xffffffffu, q, 1);
                q += __shfl_xor_sync(0xffffffffu, q, 2);
                float mu  = s * (1.0f / 16.0f);
                float var = q * (1.0f / 16.0f) - mu * mu;
                float rs  = rsqrtf(var + 1e-5f);
                float y2[4];
#pragma unroll
                for (int j = 0; j < 4; j++) {
                    int col = (j < 2) ? (cA + j) : (cB + (j - 2));
                    float y = (v[j] - mu) * rs * gamma[col] + beta[col];
                    y2[j] = y / (1.0f + expf(-y));
                }
                __half2 hA; hA.x = __float2half_rn(y2[0]); hA.y = __float2half_rn(y2[1]);
                __half2 hB; hB.x = __float2half_rn(y2[2]); hB.y = __float2half_rn(y2[3]);
                if (CIN == 64) {
                    *(__half2*)&g_h1[vox * COUT + cA] = hA;
                    *(__half2*)&g_h1[vox * COUT + cB] = hB;
                } else {
                    *(__half2*)&g_h2h[vox * COUT + cA] = hA;
                    *(__half2*)&g_h2h[vox * COUT + cB] = hB;
                }
            }
        }
    }
}

// ---------------- point branch GEMM + global group stats ------------------------
__global__ void __launch_bounds__(128)
mlp_gstats_kernel(const float* __restrict__ feats,
                  const float* __restrict__ w,
                  const float* __restrict__ bias) {
    __shared__ float s_w[CIN0 * 129];
    __shared__ float s_f[CIN0 * 32];
    const int tid = threadIdx.x;
    const int b   = blockIdx.x >> 9;
    const int n0  = (blockIdx.x & 511) * 32;

    for (int i = tid; i < COUT * CIN0; i += 128) {
        int c = i >> 6, ci = i & 63;
        s_w[ci * 129 + c] = w[i];
    }
    for (int i = tid; i < CIN0 * 32; i += 128) {
        int ci = i >> 5, p = i & 31;
        s_f[ci * 32 + p] = feats[((size_t)b * CIN0 + ci) * NN + n0 + p];
    }
    __syncthreads();

    const int c = tid;
    float bv = bias[c];
    float lsum = 0.f, lsq = 0.f;
    for (int p = 0; p < 32; p++) {
        float a = bv;
#pragma unroll 16
        for (int ci = 0; ci < CIN0; ci++)
            a += s_w[ci * 129 + c] * s_f[ci * 32 + p];
        g_pfh[((size_t)b * NN + n0 + p) * COUT + c] = __float2half_rn(a);
        lsum += a; lsq += a * a;
    }
#pragma unroll
    for (int o = 8; o >= 1; o >>= 1) {
        lsum += __shfl_xor_sync(0xffffffffu, lsum, o, 16);
        lsq  += __shfl_xor_sync(0xffffffffu, lsq,  o, 16);
    }
    if ((tid & 15) == 0) {
        int g = c >> 4;
        atomicAdd(&g_stats[(b * 8 + g) * 2 + 0], lsum);
        atomicAdd(&g_stats[(b * 8 + g) * 2 + 1], lsq);
    }
}

__global__ void stats_finalize_kernel() {
    int t = threadIdx.x;
    if (t >= BB * 8) return;
    const float inv = 1.0f / (16.0f * (float)NN);
    float s = g_stats[t * 2 + 0], s2 = g_stats[t * 2 + 1];
    float mu = s * inv;
    float var = s2 * inv - mu * mu;
    g_stats[t * 2 + 0] = mu;
    g_stats[t * 2 + 1] = rsqrtf(var + 1e-5f);
}

// ---------------- devoxelize + point GN/SiLU + add ------------------------------
__global__ void __launch_bounds__(128)
devox_out_kernel(const float* __restrict__ coords,
                 const float* __restrict__ gamma,
                 const float* __restrict__ beta,
                 float* __restrict__ out) {
    __shared__ float s_o[COUT * 17];
    const int c  = threadIdx.x;
    const int p0 = blockIdx.x * 16;
    const int b  = p0 >> 14;
    const int n0 = p0 & (NN - 1);
    const int g  = c >> 4;
    const float gm = gamma[c], bt = beta[c];
    const float mu = g_stats[(b * 8 + g) * 2 + 0];
    const float rs = g_stats[(b * 8 + g) * 2 + 1];

    for (int p = 0; p < 16; p++) {
        int gp = p0 + p;
        float cx = coords[gp * 3 + 0] * (float)RR;
        float cy = coords[gp * 3 + 1] * (float)RR;
        float cz = coords[gp * 3 + 2] * (float)RR;
        float fxl = floorf(cx), fyl = floorf(cy), fzl = floorf(cz);
        int ix = min(max((int)fxl, 0), RR - 1);
        int iy = min(max((int)fyl, 0), RR - 1);
        int iz = min(max((int)fzl, 0), RR - 1);
        int hx = min(ix + 1, RR - 1), hy = min(iy + 1, RR - 1), hz = min(iz + 1, RR - 1);
        float fx = cx - fxl, fy = cy - fyl, fz = cz - fzl;

        float v = 0.f;
#pragma unroll
        for (int dx = 0; dx < 2; dx++) {
            float wx = dx ? fx : 1.f - fx;
            int X = dx ? hx : ix;
#pragma unroll
            for (int dy = 0; dy < 2; dy++) {
                float wy = dy ? fy : 1.f - fy;
                int Y = dy ? hy : iy;
#pragma unroll
                for (int dz = 0; dz < 2; dz++) {
                    float wz = dz ? fz : 1.f - fz;
                    int Z = dz ? hz : iz;
                    size_t base = (((size_t)(b * RR + X) * RR + Y) * RR + Z) * COUT + c;
                    v += (wx * wy * wz) * __half2float(g_h2h[base]);
                }
            }
        }
        float pv = __half2float(g_pfh[((size_t)gp) * COUT + c]);
        float y  = (pv - mu) * rs * gm + bt;
        y = y / (1.0f + expf(-y));
        s_o[c * 17 + p] = v + y;
    }
    __syncthreads();
    for (int i = threadIdx.x; i < COUT * 16; i += 128) {
        int c2 = i >> 4, p = i & 15;
        out[((size_t)b * COUT + c2) * NN + n0 + p] = s_o[c2 * 17 + p];
    }
}

// ---------------- launch ----------------------------------------------------------
extern "C" void kernel_launch(void* const* d_in, const int* in_sizes, int n_in,
                              void* d_out, int out_size) {
    const float* coords   = (const float*)d_in[0];
    const float* features = (const float*)d_in[1];
    const float* conv1_w  = (const float*)d_in[2];
    const float* conv1_b  = (const float*)d_in[3];
    const float* gn1_g    = (const float*)d_in[4];
    const float* gn1_b    = (const float*)d_in[5];
    const float* conv2_w  = (const float*)d_in[6];
    const float* conv2_b  = (const float*)d_in[7];
    const float* gn2_g    = (const float*)d_in[8];
    const float* gn2_b    = (const float*)d_in[9];
    const float* mlp_w    = (const float*)d_in[10];
    const float* mlp_b    = (const float*)d_in[11];
    const float* gnp_g    = (const float*)d_in[12];
    const float* gnp_b    = (const float*)d_in[13];
    float* out = (float*)d_out;

    static int attr_done = 0;
    if (!attr_done) {
        cudaFuncSetAttribute(conv_mma_kernel<CIN0>,
                             cudaFuncAttributeMaxDynamicSharedMemorySize, CVSMEM);
        cudaFuncSetAttribute(conv_mma_kernel<COUT>,
                             cudaFuncAttributeMaxDynamicSharedMemorySize, CVSMEM);
        attr_done = 1;
    }

    // launch order: conv1 is the 4th launch -> ncu captures it.
    prep_kernel<<<4096, 256>>>(conv1_w, conv2_w);
    scatter_kernel<<<(BB * NN * CIN0 + 255) / 256, 256>>>(coords, features);
    vox_split_kernel<<<4096, 256>>>();

    dim3 cgrid(RR, 4, 2 * BB);   // x, y-tile(8), (b, z-tile(16)) -> 1024 CTAs
    conv_mma_kernel<CIN0><<<cgrid, 288, CVSMEM>>>(conv1_b, gn1_g, gn1_b);
    conv_mma_kernel<COUT><<<cgrid, 288, CVSMEM>>>(conv2_b, gn2_g, gn2_b);

    mlp_gstats_kernel<<<BB * (NN / 32), 128>>>(features, mlp_w, mlp_b);
    stats_finalize_kernel<<<1, 32>>>();

    devox_out_kernel<<<BB * NN / 16, 128>>>(coords, gnp_g, gnp_b, out);
}

// round 17
// speedup vs baseline: 1.7943x; 1.7943x over previous
#include <cuda_runtime.h>
#include <cuda_fp16.h>
#include <math.h>
#include <stdint.h>

#define BB   4
#define NN   16384
#define CIN0 64
#define COUT 128
#define RR   32
#define NVOX (BB*RR*RR*RR)   /* 131072 */

typedef unsigned int u32;
typedef unsigned long long u64;

// ---------------- scratch (device globals) ------------------------------------
__device__ float g_grid[(size_t)NVOX * CIN0];
__device__ float g_cnt [NVOX];
__device__ __align__(16) __half g_g0[(size_t)NVOX * CIN0];    // conv1 in (fp16)
__device__ __align__(16) __half g_h1[(size_t)NVOX * COUT];    // conv2 in (fp16)
__device__ __align__(16) __half g_h2h[(size_t)NVOX * COUT];   // conv2 out (fp16)
__device__ __align__(16) __half g_pfh[(size_t)BB * NN * COUT];// point feats (fp16)
__device__ float g_stats[BB * 8 * 2];
// W layouts (27 taps): conv1 [tap][co][ci64]; conv2 [ci-half][tap][co][ci64]
__device__ __align__(16) __half g_w1[27 * COUT * 64];
__device__ __align__(16) __half g_w2[2 * 27 * COUT * 64];

// ---------------- helpers -------------------------------------------------------
__device__ __forceinline__ u32 smem_u32(const void* p) {
    u32 a;
    asm("{ .reg .u64 t; cvta.to.shared.u64 t, %1; cvt.u32.u64 %0, t; }" : "=r"(a) : "l"(p));
    return a;
}
__device__ __forceinline__ void cp16(u32 dst, const void* src, u32 sz) {
    asm volatile("cp.async.cg.shared.global [%0], [%1], 16, %2;"
                 :: "r"(dst), "l"(src), "r"(sz) : "memory");
}
__device__ __forceinline__ void ldsm4(u32& r0, u32& r1, u32& r2, u32& r3, u32 a) {
    asm volatile("ldmatrix.sync.aligned.m8n8.x4.shared.b16 {%0,%1,%2,%3}, [%4];"
                 : "=r"(r0), "=r"(r1), "=r"(r2), "=r"(r3) : "r"(a));
}
__device__ __forceinline__ void mma16816(float* d,
                                         u32 a0, u32 a1, u32 a2, u32 a3,
                                         u32 b0, u32 b1) {
    asm volatile("mma.sync.aligned.m16n8k16.row.col.f32.f16.f16.f32 "
                 "{%0,%1,%2,%3}, {%4,%5,%6,%7}, {%8,%9}, {%0,%1,%2,%3};"
                 : "+f"(d[0]), "+f"(d[1]), "+f"(d[2]), "+f"(d[3])
                 : "r"(a0), "r"(a1), "r"(a2), "r"(a3), "r"(b0), "r"(b1));
}

// ---------------- prep: zero scratch + both weight preps (ONE launch) -----------
#define NG  ((long)NVOX * CIN0)
#define NC  ((long)NVOX)
#define NS  ((long)BB * 8 * 2)
#define NW1 ((long)27 * COUT * 64)
#define NW2 ((long)2 * 27 * COUT * 64)

__global__ void prep_kernel(const float* __restrict__ w1,
                            const float* __restrict__ w2) {
    const long total = NG + NC + NS + NW1 + NW2;
    for (long i = (long)blockIdx.x * blockDim.x + threadIdx.x; i < total;
         i += (long)gridDim.x * blockDim.x) {
        if (i < NG) { g_grid[i] = 0.f; continue; }
        long j = i - NG;
        if (j < NC) { g_cnt[j] = 0.f; continue; }
        j -= NC;
        if (j < NS) { g_stats[j] = 0.f; continue; }
        j -= NS;
        if (j < NW1) {
            int tap = (int)(j >> 13);            // /8192, 0..26
            int r   = (int)(j & 8191);
            int co = r >> 6, ci = r & 63;
            g_w1[j] = __float2half_rn(w1[(co * 64 + ci) * 27 + tap]);
            continue;
        }
        j -= NW1;
        {
            int q  = (int)(j >> 13);             // 0..53
            int h  = q / 27, tapl = q - h * 27;
            int r  = (int)(j & 8191);
            int co = r >> 6, ci6 = r & 63;
            g_w2[j] = __float2half_rn(w2[(co * 128 + h * 64 + ci6) * 27 + tapl]);
        }
    }
}

// ---------------- voxelize -------------------------------------------------------
__global__ void scatter_kernel(const float* __restrict__ coords,
                               const float* __restrict__ feats) {
    int idx = blockIdx.x * blockDim.x + threadIdx.x;
    if (idx >= BB * NN * CIN0) return;
    int ci = idx & (CIN0 - 1);
    int gp = idx >> 6;
    int b  = gp >> 14;
    int n  = gp & (NN - 1);
    float cx = coords[gp * 3 + 0] * (float)RR;
    float cy = coords[gp * 3 + 1] * (float)RR;
    float cz = coords[gp * 3 + 2] * (float)RR;
    int ix = min(max((int)floorf(cx), 0), RR - 1);
    int iy = min(max((int)floorf(cy), 0), RR - 1);
    int iz = min(max((int)floorf(cz), 0), RR - 1);
    int vox = ((b * RR + ix) * RR + iy) * RR + iz;
    atomicAdd(&g_grid[(size_t)vox * CIN0 + ci],
              feats[((size_t)b * CIN0 + ci) * NN + n]);
    if (ci == 0) atomicAdd(&g_cnt[vox], 1.0f);
}

__global__ void vox_split_kernel() {
    long total = (long)NVOX * CIN0;
    for (long i = (long)blockIdx.x * blockDim.x + threadIdx.x; i < total;
         i += (long)gridDim.x * blockDim.x) {
        long v = i >> 6;
        float c = g_cnt[v];
        float val = g_grid[i] * (1.0f / fmaxf(c, 1.0f));
        g_g0[i] = __float2half_rn(val);
    }
}

// ---------------- mma.sync conv (fp16) + GN + SiLU ------------------------------
// CTA: (b, x, 8y, 16z) = M128 rows x N128 couts. 256 threads = 8 warps 2M x 4N
// (warp tile M64 x N32). A: 2 streaming x-planes of 180 rows (10y x 18z) x 128B;
// next plane streamed in 8 slices of 180 16B-units during the current plane's
// taps. W: single-tap, TRIPLE buffered, prefetch distance 2 (wait_group 1) ->
// every tap's data arrives a full tap early. smem 104.6 KB -> 2 CTAs/SM.
#define PITCH    144
#define APL      (180 * PITCH)        /* 25920 */
#define WOFF     (2 * APL)            /* 51840 */
#define WTEN     (128 * PITCH)        /* 18432 */
#define CVSMEM   (WOFF + 3 * WTEN)    /* 107136 */

// prologue: group1 = {W tap0 -> buf0, A plane0}; group2 = {W tap1 -> buf1}
template <int CIN>
__device__ __forceinline__ void load_prologue(
    u32 sb, int tid, int b, int x0, int y0, int z0,
    const __half* in, const __half* wp) {
#pragma unroll
    for (int i = 0; i < 10; i++) {
        int unit = tid + i * 256;             // 2464 units
        if (unit < 1024) {                    // W tap 0
            int row = unit >> 3, c16 = unit & 7;
            cp16(sb + WOFF + row * PITCH + c16 * 16,
                 wp + (size_t)row * 64 + c16 * 8, 16u);
        } else if (unit < 2464) {             // A plane 0 (gx = x0-1, half 0)
            int au = unit - 1024;
            int row = au >> 3, c16 = au & 7;
            int yh = row / 18, zh = row - yh * 18;
            int gx = x0 - 1, gy = y0 + yh - 1, gz = z0 + zh - 1;
            bool ok = ((unsigned)gx < 32u) & ((unsigned)gy < 32u) & ((unsigned)gz < 32u);
            size_t off = 0;
            if (ok)
                off = ((((size_t)(b * 32 + gx)) * 32 + gy) * 32 + gz) * CIN + c16 * 8;
            cp16(sb + row * PITCH + c16 * 16, in + off, ok ? 16u : 0u);
        }
    }
    asm volatile("cp.async.commit_group;" ::: "memory");
#pragma unroll
    for (int i = 0; i < 4; i++) {             // W tap 1 -> buf 1
        int unit = tid + i * 256;
        int row = unit >> 3, c16 = unit & 7;
        cp16(sb + WOFF + WTEN + row * PITCH + c16 * 16,
             wp + 8192 + (size_t)row * 64 + c16 * 8, 16u);
    }
    asm volatile("cp.async.commit_group;" ::: "memory");
}

// iteration it issues: W(it+2) -> buf (it+2)%3, and A slice j=it%9 (j<8) of
// plane (it/9)+1 -> buf (np&1). Always commits exactly one group.
template <int CIN>
__device__ __forceinline__ void load_next(
    int it, u32 sb, int tid, int b, int x0, int y0, int z0,
    const __half* in, const __half* wp) {
    constexpr int NT  = 27 * (CIN / 64);
    constexpr int NPL = 3 * (CIN / 64);
    const int nit = it + 2;
    if (nit < NT) {
        const u32 wdst = sb + WOFF + (u32)(nit % 3) * WTEN;
        const __half* wsrc = wp + (size_t)nit * 8192;
#pragma unroll
        for (int i = 0; i < 4; i++) {
            int unit = tid + i * 256;
            int row = unit >> 3, c16 = unit & 7;
            cp16(wdst + row * PITCH + c16 * 16, wsrc + (size_t)row * 64 + c16 * 8, 16u);
        }
    }
    const int pl = it / 9;
    const int j  = it - 9 * pl;
    const int np = pl + 1;
    if (np < NPL && j < 8 && tid < 180) {
        int u = 180 * j + tid;                // unit within plane (0..1439)
        int row = u >> 3, c16 = u & 7;
        int yh = row / 18, zh = row - yh * 18;
        int qx = np - (np / 3) * 3;
        int hh = np / 3;
        int gx = x0 + qx - 1, gy = y0 + yh - 1, gz = z0 + zh - 1;
        bool ok = ((unsigned)gx < 32u) & ((unsigned)gy < 32u) & ((unsigned)gz < 32u);
        size_t off = 0;
        if (ok)
            off = ((((size_t)(b * 32 + gx)) * 32 + gy) * 32 + gz) * CIN
                + hh * 64 + c16 * 8;
        cp16(sb + (np & 1) * APL + row * PITCH + c16 * 16, in + off, ok ? 16u : 0u);
    }
    asm volatile("cp.async.commit_group;" ::: "memory");
}

template <int CIN>
__global__ void __launch_bounds__(256, 2)
conv_mma_kernel(const float* __restrict__ bias,
                const float* __restrict__ gamma,
                const float* __restrict__ beta) {
    extern __shared__ __align__(128) char smem[];
    constexpr int NT = 27 * (CIN / 64);
    const u32 sb = smem_u32(smem);
    const int tid = threadIdx.x, w = tid >> 5, lane = tid & 31;
    const int x0 = blockIdx.x, y0 = blockIdx.y * 8;
    const int b  = blockIdx.z >> 1, z0 = (blockIdx.z & 1) * 16;
    const int wM = w >> 2, wN = w & 3;        // 2M x 4N warp grid

    const __half* in = (CIN == 64) ? g_g0 : g_h1;
    const __half* wp = (CIN == 64) ? g_w1 : g_w2;

    float acc[4][4][4];                       // [m-tile][n8 (N32)][frag]
#pragma unroll
    for (int mt = 0; mt < 4; mt++)
#pragma unroll
        for (int nn = 0; nn < 4; nn++)
#pragma unroll
            for (int j = 0; j < 4; j++) acc[mt][nn][j] = 0.f;

    load_prologue<CIN>(sb, tid, b, x0, y0, z0, in, wp);

    const u32 b_row = (lane & 7) + ((lane >> 3) & 1) * 8;
    const u32 b_lane_off = (wN * 32 + b_row) * PITCH + (lane >> 4) * 16;

    // per-mt A row offsets (relative to plane buffer base; tap adds delta)
    u32 arel[4];
#pragma unroll
    for (int mt = 0; mt < 4; mt++)
        arel[mt] = (u32)(((wM * 4 + mt) * 18 + (lane & 15)) * PITCH)
                 + (lane >> 4) * 16;

#pragma unroll 1
    for (int it = 0; it < NT; it++) {
        asm volatile("cp.async.wait_group 1;" ::: "memory");
        __syncthreads();
        load_next<CIN>(it, sb, tid, b, x0, y0, z0, in, wp);

        const int pl   = it / 9;
        const int tapl = it - (it / 27) * 27;
        const int dy   = (tapl / 3) % 3, dz = tapl % 3;
        const u32 abase = sb + (pl & 1) * APL + (u32)((dy * 18 + dz) * PITCH);
        const u32 wbase = sb + WOFF + (u32)(it % 3) * WTEN + b_lane_off;

#pragma unroll
        for (int ks = 0; ks < 4; ks++) {
            u32 a[4][4];
#pragma unroll
            for (int mt = 0; mt < 4; mt++)
                ldsm4(a[mt][0], a[mt][1], a[mt][2], a[mt][3],
                      abase + arel[mt] + ks * 32);
#pragma unroll
            for (int nt = 0; nt < 2; nt++) {
                u32 w0, w1r, w2r, w3;
                ldsm4(w0, w1r, w2r, w3, wbase + nt * 16 * PITCH + ks * 32);
#pragma unroll
                for (int mt = 0; mt < 4; mt++) {
                    mma16816(acc[mt][2 * nt],     a[mt][0], a[mt][1], a[mt][2], a[mt][3], w0, w2r);
                    mma16816(acc[mt][2 * nt + 1], a[mt][0], a[mt][1], a[mt][2], a[mt][3], w1r, w3);
                }
            }
        }
    }

    // ---- epilogue: bias + per-voxel GN(16 ch) + SiLU, straight from fragments ----
    const int r0 = lane >> 2, cq = lane & 3;
#pragma unroll
    for (int mt = 0; mt < 4; mt++) {
        const int yl = wM * 4 + mt;
#pragma unroll
        for (int h = 0; h < 2; h++) {
            int z = r0 + h * 8;
            size_t vox = (((size_t)(b * 32 + x0)) * 32 + (y0 + yl)) * 32 + z0 + z;
#pragma unroll
            for (int k = 0; k < 2; k++) {
                int cA = wN * 32 + k * 16 + cq * 2;
                int cB = cA + 8;
                float v[4];
                v[0] = acc[mt][2 * k][2 * h + 0]     + bias[cA + 0];
                v[1] = acc[mt][2 * k][2 * h + 1]     + bias[cA + 1];
                v[2] = acc[mt][2 * k + 1][2 * h + 0] + bias[cB + 0];
                v[3] = acc[mt][2 * k + 1][2 * h + 1] + bias[cB + 1];
                float s = v[0] + v[1] + v[2] + v[3];
                float q = v[0] * v[0] + v[1] * v[1] + v[2] * v[2] + v[3] * v[3];
                s += __shfl_xor_sync(0xffffffffu, s, 1);
                s += __shfl_xor_sync(0xffffffffu, s, 2);
                q += __shfl_xor_sync(0xffffffffu, q, 1);
                q += __shfl_xor_sync(0xffffffffu, q, 2);
                float mu  = s * (1.0f / 16.0f);
                float var = q * (1.0f / 16.0f) - mu * mu;
                float rs  = rsqrtf(var + 1e-5f);
                float y2[4];
#pragma unroll
                for (int j = 0; j < 4; j++) {
                    int col = (j < 2) ? (cA + j) : (cB + (j - 2));
                    float y = (v[j] - mu) * rs * gamma[col] + beta[col];
                    y2[j] = y / (1.0f + expf(-y));
                }
                __half2 hA; hA.x = __float2half_rn(y2[0]); hA.y = __float2half_rn(y2[1]);
                __half2 hB; hB.x = __float2half_rn(y2[2]); hB.y = __float2half_rn(y2[3]);
                if (CIN == 64) {
                    *(__half2*)&g_h1[vox * COUT + cA] = hA;
                    *(__half2*)&g_h1[vox * COUT + cB] = hB;
                } else {
                    *(__half2*)&g_h2h[vox * COUT + cA] = hA;
                    *(__half2*)&g_h2h[vox * COUT + cB] = hB;
                }
            }
        }
    }
}

// ---------------- point branch GEMM + global group stats ------------------------
__global__ void __launch_bounds__(128)
mlp_gstats_kernel(const float* __restrict__ feats,
                  const float* __restrict__ w,
                  const float* __restrict__ bias) {
    __shared__ float s_w[CIN0 * 129];
    __shared__ float s_f[CIN0 * 32];
    const int tid = threadIdx.x;
    const int b   = blockIdx.x >> 9;
    const int n0  = (blockIdx.x & 511) * 32;

    for (int i = tid; i < COUT * CIN0; i += 128) {
        int c = i >> 6, ci = i & 63;
        s_w[ci * 129 + c] = w[i];
    }
    for (int i = tid; i < CIN0 * 32; i += 128) {
        int ci = i >> 5, p = i & 31;
        s_f[ci * 32 + p] = feats[((size_t)b * CIN0 + ci) * NN + n0 + p];
    }
    __syncthreads();

    const int c = tid;
    float bv = bias[c];
    float lsum = 0.f, lsq = 0.f;
    for (int p = 0; p < 32; p++) {
        float a = bv;
#pragma unroll 16
        for (int ci = 0; ci < CIN0; ci++)
            a += s_w[ci * 129 + c] * s_f[ci * 32 + p];
        g_pfh[((size_t)b * NN + n0 + p) * COUT + c] = __float2half_rn(a);
        lsum += a; lsq += a * a;
    }
#pragma unroll
    for (int o = 8; o >= 1; o >>= 1) {
        lsum += __shfl_xor_sync(0xffffffffu, lsum, o, 16);
        lsq  += __shfl_xor_sync(0xffffffffu, lsq,  o, 16);
    }
    if ((tid & 15) == 0) {
        int g = c >> 4;
        atomicAdd(&g_stats[(b * 8 + g) * 2 + 0], lsum);
        atomicAdd(&g_stats[(b * 8 + g) * 2 + 1], lsq);
    }
}

__global__ void stats_finalize_kernel() {
    int t = threadIdx.x;
    if (t >= BB * 8) return;
    const float inv = 1.0f / (16.0f * (float)NN);
    float s = g_stats[t * 2 + 0], s2 = g_stats[t * 2 + 1];
    float mu = s * inv;
    float var = s2 * inv - mu * mu;
    g_stats[t * 2 + 0] = mu;
    g_stats[t * 2 + 1] = rsqrtf(var + 1e-5f);
}

// ---------------- devoxelize + point GN/SiLU + add ------------------------------
// 128 threads: cp = tid&63 -> channels (2cp, 2cp+1) via __half2 gathers;
// ph = tid>>6 -> point half (8 points each). Halves gather request count.
__global__ void __launch_bounds__(128)
devox_out_kernel(const float* __restrict__ coords,
                 const float* __restrict__ gamma,
                 const float* __restrict__ beta,
                 float* __restrict__ out) {
    __shared__ float s_o[COUT * 17];
    const int tid = threadIdx.x;
    const int cp = tid & 63;
    const int ph = tid >> 6;
    const int c0 = cp * 2;
    const int p0 = blockIdx.x * 16;
    const int b  = p0 >> 14;
    const int n0 = p0 & (NN - 1);
    const int g  = c0 >> 4;
    const float gm0 = gamma[c0], gm1 = gamma[c0 + 1];
    const float bt0 = beta[c0],  bt1 = beta[c0 + 1];
    const float mu = g_stats[(b * 8 + g) * 2 + 0];
    const float rs = g_stats[(b * 8 + g) * 2 + 1];

    for (int pp = 0; pp < 8; pp++) {
        int p  = ph * 8 + pp;
        int gp = p0 + p;
        float cx = coords[gp * 3 + 0] * (float)RR;
        float cy = coords[gp * 3 + 1] * (float)RR;
        float cz = coords[gp * 3 + 2] * (float)RR;
        float fxl = floorf(cx), fyl = floorf(cy), fzl = floorf(cz);
        int ix = min(max((int)fxl, 0), RR - 1);
        int iy = min(max((int)fyl, 0), RR - 1);
        int iz = min(max((int)fzl, 0), RR - 1);
        int hx = min(ix + 1, RR - 1), hy = min(iy + 1, RR - 1), hz = min(iz + 1, RR - 1);
        float fx = cx - fxl, fy = cy - fyl, fz = cz - fzl;

        float v0 = 0.f, v1 = 0.f;
#pragma unroll
        for (int dx = 0; dx < 2; dx++) {
            float wx = dx ? fx : 1.f - fx;
            int X = dx ? hx : ix;
#pragma unroll
            for (int dy = 0; dy < 2; dy++) {
                float wy = dy ? fy : 1.f - fy;
                int Y = dy ? hy : iy;
#pragma unroll
                for (int dz = 0; dz < 2; dz++) {
                    float wz = dz ? fz : 1.f - fz;
                    int Z = dz ? hz : iz;
                    size_t base = (((size_t)(b * RR + X) * RR + Y) * RR + Z) * COUT + c0;
                    __half2 hv = *(const __half2*)&g_h2h[base];
                    float2 fv = __half22float2(hv);
                    float ww = wx * wy * wz;
                    v0 += ww * fv.x;
                    v1 += ww * fv.y;
                }
            }
        }
        __half2 pvh = *(const __half2*)&g_pfh[(size_t)gp * COUT + c0];
        float2 pv = __half22float2(pvh);
        float ya = (pv.x - mu) * rs * gm0 + bt0;
        float yb = (pv.y - mu) * rs * gm1 + bt1;
        ya = ya / (1.0f + expf(-ya));
        yb = yb / (1.0f + expf(-yb));
        s_o[c0 * 17 + p]       = v0 + ya;
        s_o[(c0 + 1) * 17 + p] = v1 + yb;
    }
    __syncthreads();
    for (int i = tid; i < COUT * 16; i += 128) {
        int c2 = i >> 4, p = i & 15;
        out[((size_t)b * COUT + c2) * NN + n0 + p] = s_o[c2 * 17 + p];
    }
}

// ---------------- launch ----------------------------------------------------------
extern "C" void kernel_launch(void* const* d_in, const int* in_sizes, int n_in,
                              void* d_out, int out_size) {
    const float* coords   = (const float*)d_in[0];
    const float* features = (const float*)d_in[1];
    const float* conv1_w  = (const float*)d_in[2];
    const float* conv1_b  = (const float*)d_in[3];
    const float* gn1_g    = (const float*)d_in[4];
    const float* gn1_b    = (const float*)d_in[5];
    const float* conv2_w  = (const float*)d_in[6];
    const float* conv2_b  = (const float*)d_in[7];
    const float* gn2_g    = (const float*)d_in[8];
    const float* gn2_b    = (const float*)d_in[9];
    const float* mlp_w    = (const float*)d_in[10];
    const float* mlp_b    = (const float*)d_in[11];
    const float* gnp_g    = (const float*)d_in[12];
    const float* gnp_b    = (const float*)d_in[13];
    float* out = (float*)d_out;

    static int attr_done = 0;
    if (!attr_done) {
        cudaFuncSetAttribute(conv_mma_kernel<CIN0>,
                             cudaFuncAttributeMaxDynamicSharedMemorySize, CVSMEM);
        cudaFuncSetAttribute(conv_mma_kernel<COUT>,
                             cudaFuncAttributeMaxDynamicSharedMemorySize, CVSMEM);
        attr_done = 1;
    }

    // launch order: conv1 is the 4th launch -> ncu captures it.
    prep_kernel<<<4096, 256>>>(conv1_w, conv2_w);
    scatter_kernel<<<(BB * NN * CIN0 + 255) / 256, 256>>>(coords, features);
    vox_split_kernel<<<4096, 256>>>();

    dim3 cgrid(RR, 4, 2 * BB);   // x, y-tile(8), (b, z-tile(16)) -> 1024 CTAs
    conv_mma_kernel<CIN0><<<cgrid, 256, CVSMEM>>>(conv1_b, gn1_g, gn1_b);
    conv_mma_kernel<COUT><<<cgrid, 256, CVSMEM>>>(conv2_b, gn2_g, gn2_b);

    mlp_gstats_kernel<<<BB * (NN / 32), 128>>>(features, mlp_w, mlp_b);
    stats_finalize_kernel<<<1, 32>>>();

    devox_out_kernel<<<BB * NN / 16, 128>>>(coords, gnp_g, gnp_b, out);
}